// round 1
// baseline (speedup 1.0000x reference)
#include <cuda_runtime.h>
#include <cuda_bf16.h>

// 4D conv (VALID, stride 1) + ReLU
// in  : [2,16,8,8,64,64] f32
// wgt : [32,16,3,3,3,3]  f32
// out : [2,32,6,6,62,62] f32
//
// Decomposition: block = (b, z1, z2, 16x16 hw tile). Loop over (c,i,j) slabs
// (144), staging an 18x18 input slab + 32x9 weights in smem. Each thread
// accumulates 8 oc x 2x2 pixels in registers.

#define B_   2
#define C_   16
#define D1_  8
#define D2_  8
#define H_   64
#define W_   64
#define O_   32
#define Z1_  6
#define Z2_  6
#define OH_  62
#define OW_  62

#define TILE    16
#define SLAB    18          // TILE + 2
#define SLABP   19          // padded row stride
#define NW      288         // 32 oc * 9 taps

__global__ __launch_bounds__(256, 4)
void conv4d_relu_kernel(const float* __restrict__ x,
                        const float* __restrict__ wgt,
                        float* __restrict__ out)
{
    __shared__ float sx[SLAB * SLABP];   // 18 x 19
    __shared__ float sw_[NW];            // [oc][9]

    const int tid = threadIdx.x;

    // block decode
    const int zb = blockIdx.z;           // 0..71
    const int b  = zb / 36;
    const int zr = zb % 36;
    const int z1 = zr / 6;
    const int z2 = zr % 6;
    const int h0 = blockIdx.y * TILE;
    const int w0 = blockIdx.x * TILE;

    // thread decode: 4 oc-groups x 64 pixel-threads
    const int ocg = tid >> 6;            // 0..3 -> oc base = ocg*8
    const int p   = tid & 63;
    const int ph  = p >> 3;              // 0..7 -> rows 2ph, 2ph+1
    const int pw  = p & 7;               // 0..7 -> cols 2pw, 2pw+1

    float acc[8][2][2];
#pragma unroll
    for (int o = 0; o < 8; o++)
#pragma unroll
        for (int dy = 0; dy < 2; dy++)
#pragma unroll
            for (int dx = 0; dx < 2; dx++)
                acc[o][dy][dx] = 0.f;

    const int swbase = (ocg * 8) * 9;    // warp-uniform weight base

#pragma unroll 1
    for (int c = 0; c < C_; c++) {
#pragma unroll 1
        for (int i = 0; i < 3; i++) {
#pragma unroll 1
            for (int j = 0; j < 3; j++) {
                // ---- stage input slab: x[b,c,z1+i,z2+j, h0..h0+17, w0..w0+17]
                const long in_base =
                    ((((long)b * C_ + c) * D1_ + (z1 + i)) * D2_ + (z2 + j)) * (H_ * W_);
                for (int idx = tid; idx < SLAB * SLAB; idx += 256) {
                    const int rr = idx / SLAB;
                    const int cc = idx - rr * SLAB;
                    const int gr = h0 + rr;
                    const int gc = w0 + cc;
                    float v = 0.f;
                    if (gr < H_ && gc < W_)
                        v = x[in_base + gr * W_ + gc];
                    sx[rr * SLABP + cc] = v;
                }
                // ---- stage weights: wgt[oc, c, i, j, 0..8] for all 32 oc
                {
                    const int wb = c * 81 + i * 27 + j * 9;
                    int idx = tid;
                    if (idx < NW) {
                        const int oc = idx / 9;
                        const int t  = idx - oc * 9;
                        sw_[idx] = wgt[oc * 1296 + wb + t];
                    }
                    idx = tid + 256;
                    if (idx < NW) {
                        const int oc = idx / 9;
                        const int t  = idx - oc * 9;
                        sw_[idx] = wgt[oc * 1296 + wb + t];
                    }
                }
                __syncthreads();

                // ---- accumulate 9 taps x 8 oc x 4 pixels
#pragma unroll
                for (int k = 0; k < 3; k++) {
#pragma unroll
                    for (int l = 0; l < 3; l++) {
                        const int rbase = (2 * ph + k) * SLABP + (2 * pw + l);
                        const float x00 = sx[rbase];
                        const float x01 = sx[rbase + 1];
                        const float x10 = sx[rbase + SLABP];
                        const float x11 = sx[rbase + SLABP + 1];
                        const int wb2 = swbase + k * 3 + l;
#pragma unroll
                        for (int o = 0; o < 8; o++) {
                            const float wv = sw_[wb2 + o * 9];
                            acc[o][0][0] = fmaf(x00, wv, acc[o][0][0]);
                            acc[o][0][1] = fmaf(x01, wv, acc[o][0][1]);
                            acc[o][1][0] = fmaf(x10, wv, acc[o][1][0]);
                            acc[o][1][1] = fmaf(x11, wv, acc[o][1][1]);
                        }
                    }
                }
                __syncthreads();
            }
        }
    }

    // ---- ReLU + store
    const long ob0 = (((long)b * O_ + ocg * 8) * (Z1_ * Z2_) + (z1 * Z2_ + z2)) * (OH_ * OW_);
#pragma unroll
    for (int o = 0; o < 8; o++) {
        const long obase = ob0 + (long)o * (Z1_ * Z2_ * OH_ * OW_);
#pragma unroll
        for (int dy = 0; dy < 2; dy++) {
            const int py = h0 + 2 * ph + dy;
            if (py >= OH_) continue;
#pragma unroll
            for (int dx = 0; dx < 2; dx++) {
                const int px = w0 + 2 * pw + dx;
                if (px >= OW_) continue;
                out[obase + py * OW_ + px] = fmaxf(acc[o][dy][dx], 0.f);
            }
        }
    }
}

extern "C" void kernel_launch(void* const* d_in, const int* in_sizes, int n_in,
                              void* d_out, int out_size)
{
    const float* x   = (const float*)d_in[0];
    const float* wgt = (const float*)d_in[1];
    float* out = (float*)d_out;

    dim3 grid(4, 4, B_ * Z1_ * Z2_);   // (4,4,72)
    conv4d_relu_kernel<<<grid, 256>>>(x, wgt, out);
}

// round 2
// speedup vs baseline: 1.1263x; 1.1263x over previous
#include <cuda_runtime.h>
#include <cuda_bf16.h>

// 4D conv (VALID, stride 1) + ReLU — f32x2-packed FFMA version
// in  : [2,16,8,8,64,64] f32
// wgt : [32,16,3,3,3,3]  f32
// out : [2,32,6,6,62,62] f32
//
// Block = (b, z1, z2, 16x16 hw tile). Loop over 144 (c,i,j) slabs staging an
// 18x18 input slab + 32x9 weights (transposed, [tap][oc]) in smem.
// Thread = 4 oc-PAIRS x 2x2 pixels, accumulated as packed f32x2; weights for
// an oc pair come from one LDS.64. Input 4x4 footprint loaded once per slab.

#define B_   2
#define C_   16
#define D1_  8
#define D2_  8
#define H_   64
#define W_   64
#define O_   32
#define Z1_  6
#define Z2_  6
#define OH_  62
#define OW_  62

#define TILE    16
#define SLAB    18          // TILE + 2
#define SLABP   19          // padded row stride
#define NW      288         // 9 taps * 32 oc

typedef unsigned long long u64;

__device__ __forceinline__ u64 pack2(float a, float b) {
    u64 r;
    asm("mov.b64 %0, {%1, %2};" : "=l"(r) : "f"(a), "f"(b));
    return r;
}
__device__ __forceinline__ void unpack2(float& lo, float& hi, u64 v) {
    asm("mov.b64 {%0, %1}, %2;" : "=f"(lo), "=f"(hi) : "l"(v));
}
__device__ __forceinline__ u64 fma2(u64 a, u64 b, u64 c) {
    u64 d;
    asm("fma.rn.f32x2 %0, %1, %2, %3;" : "=l"(d) : "l"(a), "l"(b), "l"(c));
    return d;
}

__global__ __launch_bounds__(256, 3)
void conv4d_relu_f32x2_kernel(const float* __restrict__ x,
                              const float* __restrict__ wgt,
                              float* __restrict__ out)
{
    __shared__ float sx[SLAB * SLABP];              // 18 x 19
    __shared__ __align__(8) float sw2[NW];          // [tap][oc]

    const int tid = threadIdx.x;

    // block decode
    const int zb = blockIdx.z;           // 0..71
    const int b  = zb / 36;
    const int zr = zb % 36;
    const int z1 = zr / 6;
    const int z2 = zr % 6;
    const int h0 = blockIdx.y * TILE;
    const int w0 = blockIdx.x * TILE;

    // thread decode: 4 oc-groups x 64 pixel-threads
    const int ocg = tid >> 6;            // 0..3 -> oc base = ocg*8
    const int p   = tid & 63;
    const int ph  = p >> 3;              // rows 2ph, 2ph+1
    const int pw  = p & 7;               // cols 2pw, 2pw+1

    // 4 oc-pairs x 2x2 pixels, packed
    u64 acc[4][2][2];
#pragma unroll
    for (int op = 0; op < 4; op++)
#pragma unroll
        for (int dy = 0; dy < 2; dy++)
#pragma unroll
            for (int dx = 0; dx < 2; dx++)
                acc[op][dy][dx] = 0ull;

    const u64* __restrict__ swq = (const u64*)sw2;
    const int wqbase = ocg * 4;          // oc-pair base within a tap row (16 pairs/tap)
    const int xbase  = (2 * ph) * SLABP + 2 * pw;

#pragma unroll 1
    for (int c = 0; c < C_; c++) {
#pragma unroll 1
        for (int i = 0; i < 3; i++) {
#pragma unroll 1
            for (int j = 0; j < 3; j++) {
                // ---- stage input slab
                const long in_base =
                    ((((long)b * C_ + c) * D1_ + (z1 + i)) * D2_ + (z2 + j)) * (H_ * W_);
                for (int idx = tid; idx < SLAB * SLAB; idx += 256) {
                    const int rr = idx / SLAB;
                    const int cc = idx - rr * SLAB;
                    const int gr = h0 + rr;
                    const int gc = w0 + cc;
                    float v = 0.f;
                    if (gr < H_ && gc < W_)
                        v = x[in_base + gr * W_ + gc];
                    sx[rr * SLABP + cc] = v;
                }
                // ---- stage weights transposed: sw2[t*32 + oc]
                if (tid < NW) {
                    const int oc = tid / 9;
                    const int t  = tid - oc * 9;
                    sw2[t * 32 + oc] =
                        wgt[oc * 1296 + c * 81 + i * 27 + j * 9 + t];
                }
                if (tid + 256 < NW) {
                    const int idx = tid + 256;
                    const int oc = idx / 9;
                    const int t  = idx - oc * 9;
                    sw2[t * 32 + oc] =
                        wgt[oc * 1296 + c * 81 + i * 27 + j * 9 + t];
                }
                __syncthreads();

                // ---- load 4x4 input footprint once
                float xf[4][4];
#pragma unroll
                for (int r = 0; r < 4; r++)
#pragma unroll
                    for (int cc = 0; cc < 4; cc++)
                        xf[r][cc] = sx[xbase + r * SLABP + cc];

                // ---- 9 taps x 4 oc-pairs x 4 pixels, packed FMA
#pragma unroll
                for (int k = 0; k < 3; k++) {
#pragma unroll
                    for (int l = 0; l < 3; l++) {
                        const int t = k * 3 + l;
                        const u64 wp0 = swq[t * 16 + wqbase + 0];
                        const u64 wp1 = swq[t * 16 + wqbase + 1];
                        const u64 wp2 = swq[t * 16 + wqbase + 2];
                        const u64 wp3 = swq[t * 16 + wqbase + 3];
#pragma unroll
                        for (int dy = 0; dy < 2; dy++) {
#pragma unroll
                            for (int dx = 0; dx < 2; dx++) {
                                const float xv = xf[k + dy][l + dx];
                                const u64 xx = pack2(xv, xv);
                                acc[0][dy][dx] = fma2(xx, wp0, acc[0][dy][dx]);
                                acc[1][dy][dx] = fma2(xx, wp1, acc[1][dy][dx]);
                                acc[2][dy][dx] = fma2(xx, wp2, acc[2][dy][dx]);
                                acc[3][dy][dx] = fma2(xx, wp3, acc[3][dy][dx]);
                            }
                        }
                    }
                }
                __syncthreads();
            }
        }
    }

    // ---- ReLU + store
    const int ocb = ocg * 8;
    const long plane = (long)Z1_ * Z2_ * OH_ * OW_;
    const long ob0 = (((long)b * O_ + ocb) * (Z1_ * Z2_) + (z1 * Z2_ + z2)) * (OH_ * OW_);
#pragma unroll
    for (int op = 0; op < 4; op++) {
        const long obase0 = ob0 + (long)(2 * op)     * plane;
        const long obase1 = ob0 + (long)(2 * op + 1) * plane;
#pragma unroll
        for (int dy = 0; dy < 2; dy++) {
            const int py = h0 + 2 * ph + dy;
            if (py >= OH_) continue;
#pragma unroll
            for (int dx = 0; dx < 2; dx++) {
                const int px = w0 + 2 * pw + dx;
                if (px >= OW_) continue;
                float lo, hi;
                unpack2(lo, hi, acc[op][dy][dx]);
                out[obase0 + py * OW_ + px] = fmaxf(lo, 0.f);
                out[obase1 + py * OW_ + px] = fmaxf(hi, 0.f);
            }
        }
    }
}

extern "C" void kernel_launch(void* const* d_in, const int* in_sizes, int n_in,
                              void* d_out, int out_size)
{
    const float* x   = (const float*)d_in[0];
    const float* wgt = (const float*)d_in[1];
    float* out = (float*)d_out;

    dim3 grid(4, 4, B_ * Z1_ * Z2_);   // (4,4,72)
    conv4d_relu_f32x2_kernel<<<grid, 256>>>(x, wgt, out);
}

// round 4
// speedup vs baseline: 1.2543x; 1.1137x over previous
#include <cuda_runtime.h>
#include <cuda_bf16.h>

// 4D conv (VALID, stride 1) + ReLU — f32x2 FFMA, software-pipelined staging.
// in  : [2,16,8,8,64,64] f32
// wgt : [32,16,3,3,3,3]  f32
// out : [2,32,6,6,62,62] f32
//
// Block = (b, z1, z2, 16x16 hw tile). 144 (c,i,j) slabs. Double-buffered smem:
// while computing slab s from buf[s&1], the LDGs for slab s+1 are in flight;
// STS into buf[(s+1)&1] after compute, one __syncthreads per slab.
// FIX vs prev round: weights need 288 elements staged -> threads 0..31 stage
// a SECOND weight element (256..287).

#define B_   2
#define C_   16
#define D1_  8
#define D2_  8
#define H_   64
#define W_   64
#define O_   32
#define Z1_  6
#define Z2_  6
#define OH_  62
#define OW_  62

#define TILE    16
#define SLAB    18
#define SLABP   19
#define SLABN   (SLAB * SLAB)     // 324
#define NW      288               // 9 taps * 32 oc
#define NSLABS  144               // C_ * 9

typedef unsigned long long u64;

__device__ __forceinline__ u64 pack2(float a, float b) {
    u64 r;
    asm("mov.b64 %0, {%1, %2};" : "=l"(r) : "f"(a), "f"(b));
    return r;
}
__device__ __forceinline__ void unpack2(float& lo, float& hi, u64 v) {
    asm("mov.b64 {%0, %1}, %2;" : "=f"(lo), "=f"(hi) : "l"(v));
}
__device__ __forceinline__ u64 fma2(u64 a, u64 b, u64 c) {
    u64 d;
    asm("fma.rn.f32x2 %0, %1, %2, %3;" : "=l"(d) : "l"(a), "l"(b), "l"(c));
    return d;
}

__global__ __launch_bounds__(256, 3)
void conv4d_relu_pipe_kernel(const float* __restrict__ x,
                             const float* __restrict__ wgt,
                             float* __restrict__ out)
{
    __shared__ float sx[2][SLAB * SLABP];
    __shared__ __align__(16) float sw2[2][NW];   // [tap][oc], transposed

    const int tid = threadIdx.x;

    // ---- block decode
    const int zb = blockIdx.z;
    const int b  = zb / 36;
    const int zr = zb % 36;
    const int z1 = zr / 6;
    const int z2 = zr % 6;
    const int h0 = blockIdx.y * TILE;
    const int w0 = blockIdx.x * TILE;

    // ---- thread decode: 4 oc-groups x 64 pixel-threads
    const int ocg = tid >> 6;
    const int p   = tid & 63;
    const int ph  = p >> 3;
    const int pw  = p & 7;

    // ---- per-thread staging constants (fixed across all 144 slabs)
    // x staging: elements tid and tid+256 of the 324-elem slab
    const int rr0 = tid / SLAB,        cc0 = tid - rr0 * SLAB;
    const int idx1 = tid + 256;
    const bool has1 = (idx1 < SLABN);
    const int rr1 = idx1 / SLAB,       cc1 = idx1 - rr1 * SLAB;
    const bool v0 = (h0 + rr0 < H_) && (w0 + cc0 < W_);
    const bool v1 = has1 && (h0 + rr1 < H_) && (w0 + cc1 < W_);
    const int xoff0 = (h0 + rr0) * W_ + (w0 + cc0);
    const int xoff1 = (h0 + rr1) * W_ + (w0 + cc1);
    const int sdst0 = rr0 * SLABP + cc0;
    const int sdst1 = rr1 * SLABP + cc1;
    // weight staging: element tid, plus element tid+256 for tid<32
    const int woc0 = tid / 9;
    const int wt0  = tid - woc0 * 9;
    const int wsrc0 = woc0 * 1296 + wt0;     // + (c*81 + i*27 + j*9)
    const int wdst0 = wt0 * 32 + woc0;
    const bool hw1 = (tid + 256 < NW);       // tid < 32
    const int widx1 = tid + 256;
    const int woc1 = widx1 / 9;
    const int wt1  = widx1 - woc1 * 9;
    const int wsrc1 = woc1 * 1296 + wt1;
    const int wdst1 = wt1 * 32 + woc1;

    // slab s -> global offsets
    const long base0 = ((((long)b * C_) * D1_ + z1) * D2_ + z2) * (H_ * W_);

    // ---- accumulators: 4 oc-pairs x 2x2 pixels
    u64 acc[4][2][2];
#pragma unroll
    for (int o = 0; o < 4; o++)
#pragma unroll
        for (int dy = 0; dy < 2; dy++)
#pragma unroll
            for (int dx = 0; dx < 2; dx++)
                acc[o][dy][dx] = 0ull;

    const int xbase = (2 * ph) * SLABP + 2 * pw;

    // ---- prologue: stage slab 0 (c=0,i=0,j=0)
    {
        float px0 = v0 ? x[base0 + xoff0] : 0.f;
        float px1 = v1 ? x[base0 + xoff1] : 0.f;
        float pw0 = wgt[wsrc0];
        float pw1 = hw1 ? wgt[wsrc1] : 0.f;
        sx[0][sdst0] = px0;
        if (has1) sx[0][sdst1] = px1;
        sw2[0][wdst0] = pw0;
        if (hw1) sw2[0][wdst1] = pw1;
    }
    __syncthreads();

#pragma unroll 1
    for (int s = 0; s < NSLABS; s++) {
        // ---- prefetch slab s+1 into registers
        float px0 = 0.f, px1 = 0.f, pw0 = 0.f, pw1 = 0.f;
        if (s + 1 < NSLABS) {
            const int sn = s + 1;
            const int c  = sn / 9;
            const int r9 = sn - c * 9;
            const int i  = r9 / 3;
            const int j  = r9 - i * 3;
            const long in_base = base0
                + (long)c * (D1_ * D2_ * H_ * W_)
                + i * (D2_ * H_ * W_)
                + j * (H_ * W_);
            const int wofs = c * 81 + i * 27 + j * 9;
            px0 = v0 ? x[in_base + xoff0] : 0.f;
            px1 = v1 ? x[in_base + xoff1] : 0.f;
            pw0 = wgt[wsrc0 + wofs];
            pw1 = hw1 ? wgt[wsrc1 + wofs] : 0.f;
        }

        // ---- compute slab s from buffer s&1
        const float* __restrict__ sxp = sx[s & 1];
        const ulonglong2* __restrict__ swq2 = (const ulonglong2*)sw2[s & 1];

        float xf[4][4];
#pragma unroll
        for (int r = 0; r < 4; r++)
#pragma unroll
            for (int cc = 0; cc < 4; cc++)
                xf[r][cc] = sxp[xbase + r * SLABP + cc];

#pragma unroll
        for (int k = 0; k < 3; k++) {
#pragma unroll
            for (int l = 0; l < 3; l++) {
                const int t = k * 3 + l;
                // 4 oc-pairs for this tap: two LDS.128 (warp-uniform broadcast)
                const ulonglong2 wA = swq2[t * 8 + ocg * 2];
                const ulonglong2 wB = swq2[t * 8 + ocg * 2 + 1];
#pragma unroll
                for (int dy = 0; dy < 2; dy++) {
#pragma unroll
                    for (int dx = 0; dx < 2; dx++) {
                        const float xv = xf[k + dy][l + dx];
                        const u64 xx = pack2(xv, xv);
                        acc[0][dy][dx] = fma2(xx, wA.x, acc[0][dy][dx]);
                        acc[1][dy][dx] = fma2(xx, wA.y, acc[1][dy][dx]);
                        acc[2][dy][dx] = fma2(xx, wB.x, acc[2][dy][dx]);
                        acc[3][dy][dx] = fma2(xx, wB.y, acc[3][dy][dx]);
                    }
                }
            }
        }

        // ---- store prefetched slab s+1 into the other buffer
        if (s + 1 < NSLABS) {
            const int q = (s + 1) & 1;
            sx[q][sdst0] = px0;
            if (has1) sx[q][sdst1] = px1;
            sw2[q][wdst0] = pw0;
            if (hw1) sw2[q][wdst1] = pw1;
        }
        __syncthreads();
    }

    // ---- ReLU + store
    const int ocb = ocg * 8;
    const long plane = (long)Z1_ * Z2_ * OH_ * OW_;
    const long ob0 = (((long)b * O_ + ocb) * (Z1_ * Z2_) + (z1 * Z2_ + z2)) * (OH_ * OW_);
#pragma unroll
    for (int o = 0; o < 4; o++) {
        const long obase0 = ob0 + (long)(2 * o)     * plane;
        const long obase1 = ob0 + (long)(2 * o + 1) * plane;
#pragma unroll
        for (int dy = 0; dy < 2; dy++) {
            const int py = h0 + 2 * ph + dy;
            if (py >= OH_) continue;
#pragma unroll
            for (int dx = 0; dx < 2; dx++) {
                const int px = w0 + 2 * pw + dx;
                if (px >= OW_) continue;
                float lo, hi;
                unpack2(lo, hi, acc[o][dy][dx]);
                out[obase0 + py * OW_ + px] = fmaxf(lo, 0.f);
                out[obase1 + py * OW_ + px] = fmaxf(hi, 0.f);
            }
        }
    }
}

extern "C" void kernel_launch(void* const* d_in, const int* in_sizes, int n_in,
                              void* d_out, int out_size)
{
    const float* x   = (const float*)d_in[0];
    const float* wgt = (const float*)d_in[1];
    float* out = (float*)d_out;

    dim3 grid(4, 4, B_ * Z1_ * Z2_);   // (4,4,72)
    conv4d_relu_pipe_kernel<<<grid, 256>>>(x, wgt, out);
}

// round 5
// speedup vs baseline: 1.4749x; 1.1758x over previous
#include <cuda_runtime.h>
#include <cuda_bf16.h>

// 4D conv (VALID, stride 1) + ReLU — f32x2 FFMA, pipelined, fat oc-tile.
// in  : [2,16,8,8,64,64] f32
// wgt : [32,16,3,3,3,3]  f32
// out : [2,32,6,6,62,62] f32
//
// Block = (b, z1, z2, 16x32 hw tile), 256 threads = 2 ocg(16 oc) x 128
// pixel-threads (2x2 px). 144 (c,t1,t2) slabs, double-buffered smem with
// register prefetch. Per slab per thread: 288 FFMA2, 16 x-LDS, 36 broadcast
// weight LDS.128 -> fma pipe becomes the binding pipe.

#define B_   2
#define C_   16
#define D1_  8
#define D2_  8
#define H_   64
#define W_   64
#define O_   32
#define Z1_  6
#define Z2_  6
#define OH_  62
#define OW_  62

#define TH      16            // tile height
#define TW      32            // tile width
#define SLABH   18            // TH + 2
#define SLABW   34            // TW + 2
#define SLABP   35            // padded row stride (odd)
#define SLABN   (SLABH * SLABW)   // 612
#define NW      288               // 9 taps * 32 oc
#define NSLABS  144               // C_ * 9

typedef unsigned long long u64;

__device__ __forceinline__ u64 pack2(float a, float b) {
    u64 r;
    asm("mov.b64 %0, {%1, %2};" : "=l"(r) : "f"(a), "f"(b));
    return r;
}
__device__ __forceinline__ void unpack2(float& lo, float& hi, u64 v) {
    asm("mov.b64 {%0, %1}, %2;" : "=f"(lo), "=f"(hi) : "l"(v));
}
__device__ __forceinline__ u64 fma2(u64 a, u64 b, u64 c) {
    u64 d;
    asm("fma.rn.f32x2 %0, %1, %2, %3;" : "=l"(d) : "l"(a), "l"(b), "l"(c));
    return d;
}

__global__ __launch_bounds__(256, 2)
void conv4d_relu_fat_kernel(const float* __restrict__ x,
                            const float* __restrict__ wgt,
                            float* __restrict__ out)
{
    __shared__ float sx[2][SLABH * SLABP];
    __shared__ __align__(16) float sw2[2][NW];   // [tap][oc], transposed

    const int tid = threadIdx.x;

    // ---- block decode
    const int zb = blockIdx.z;
    const int b  = zb / 36;
    const int zr = zb % 36;
    const int z1 = zr / 6;
    const int z2 = zr % 6;
    const int h0 = blockIdx.y * TH;
    const int w0 = blockIdx.x * TW;

    // ---- thread decode: 2 oc-groups x 128 pixel-threads (2x2 px each)
    const int ocg = tid >> 7;            // 0..1 -> oc base = ocg*16
    const int p   = tid & 127;
    const int ph  = p >> 4;              // 0..7  -> rows 2ph, 2ph+1
    const int pw  = p & 15;              // 0..15 -> cols 2pw, 2pw+1

    // ---- per-thread staging constants
    // x staging: elements tid, tid+256, tid+512 of the 612-elem slab
    const int rr0 = tid / SLABW,  cc0 = tid - rr0 * SLABW;
    const int i1 = tid + 256;
    const int rr1 = i1 / SLABW,   cc1 = i1 - rr1 * SLABW;
    const int i2 = tid + 512;
    const bool has2 = (i2 < SLABN);
    const int rr2 = has2 ? i2 / SLABW : 0;
    const int cc2 = has2 ? i2 - rr2 * SLABW : 0;
    const bool v0 = (h0 + rr0 < H_) && (w0 + cc0 < W_);
    const bool v1 = (h0 + rr1 < H_) && (w0 + cc1 < W_);
    const bool v2 = has2 && (h0 + rr2 < H_) && (w0 + cc2 < W_);
    const int xoff0 = (h0 + rr0) * W_ + (w0 + cc0);
    const int xoff1 = (h0 + rr1) * W_ + (w0 + cc1);
    const int xoff2 = (h0 + rr2) * W_ + (w0 + cc2);
    const int sdst0 = rr0 * SLABP + cc0;
    const int sdst1 = rr1 * SLABP + cc1;
    const int sdst2 = rr2 * SLABP + cc2;
    // weight staging: element tid, plus tid+256 for tid<32
    const int woc0 = tid / 9;
    const int wt0  = tid - woc0 * 9;
    const int wsrc0 = woc0 * 1296 + wt0;
    const int wdst0 = wt0 * 32 + woc0;
    const bool hw1 = (tid + 256 < NW);
    const int wi1  = tid + 256;
    const int woc1 = wi1 / 9;
    const int wt1  = wi1 - woc1 * 9;
    const int wsrc1 = woc1 * 1296 + wt1;
    const int wdst1 = wt1 * 32 + woc1;

    const long base0 = ((((long)b * C_) * D1_ + z1) * D2_ + z2) * (H_ * W_);

    // ---- accumulators: 8 oc-pairs x 2x2 pixels
    u64 acc[8][2][2];
#pragma unroll
    for (int o = 0; o < 8; o++)
#pragma unroll
        for (int dy = 0; dy < 2; dy++)
#pragma unroll
            for (int dx = 0; dx < 2; dx++)
                acc[o][dy][dx] = 0ull;

    const int xbase = (2 * ph) * SLABP + 2 * pw;

    // ---- prologue: stage slab 0
    {
        float a0 = v0 ? x[base0 + xoff0] : 0.f;
        float a1 = v1 ? x[base0 + xoff1] : 0.f;
        float a2 = v2 ? x[base0 + xoff2] : 0.f;
        float q0 = wgt[wsrc0];
        float q1 = hw1 ? wgt[wsrc1] : 0.f;
        sx[0][sdst0] = a0;
        sx[0][sdst1] = a1;
        if (has2) sx[0][sdst2] = a2;
        sw2[0][wdst0] = q0;
        if (hw1) sw2[0][wdst1] = q1;
    }
    __syncthreads();

#pragma unroll 1
    for (int s = 0; s < NSLABS; s++) {
        // ---- prefetch slab s+1 into registers
        float a0 = 0.f, a1 = 0.f, a2 = 0.f, q0 = 0.f, q1 = 0.f;
        if (s + 1 < NSLABS) {
            const int sn = s + 1;
            const int c  = sn / 9;
            const int r9 = sn - c * 9;
            const int i  = r9 / 3;
            const int j  = r9 - i * 3;
            const long in_base = base0
                + (long)c * (D1_ * D2_ * H_ * W_)
                + i * (D2_ * H_ * W_)
                + j * (H_ * W_);
            const int wofs = c * 81 + i * 27 + j * 9;
            a0 = v0 ? x[in_base + xoff0] : 0.f;
            a1 = v1 ? x[in_base + xoff1] : 0.f;
            a2 = v2 ? x[in_base + xoff2] : 0.f;
            q0 = wgt[wsrc0 + wofs];
            q1 = hw1 ? wgt[wsrc1 + wofs] : 0.f;
        }

        // ---- compute slab s
        const float* __restrict__ sxp = sx[s & 1];
        const ulonglong2* __restrict__ swq2 = (const ulonglong2*)sw2[s & 1];

        float xf[4][4];
#pragma unroll
        for (int r = 0; r < 4; r++)
#pragma unroll
            for (int cc = 0; cc < 4; cc++)
                xf[r][cc] = sxp[xbase + r * SLABP + cc];

#pragma unroll
        for (int k = 0; k < 3; k++) {
#pragma unroll
            for (int l = 0; l < 3; l++) {
                const int t = k * 3 + l;
                // 8 oc-pairs for this tap: four broadcast LDS.128
                const ulonglong2 wA = swq2[t * 8 + ocg * 4 + 0];
                const ulonglong2 wB = swq2[t * 8 + ocg * 4 + 1];
                const ulonglong2 wC = swq2[t * 8 + ocg * 4 + 2];
                const ulonglong2 wD = swq2[t * 8 + ocg * 4 + 3];
#pragma unroll
                for (int dy = 0; dy < 2; dy++) {
#pragma unroll
                    for (int dx = 0; dx < 2; dx++) {
                        const float xv = xf[k + dy][l + dx];
                        const u64 xx = pack2(xv, xv);
                        acc[0][dy][dx] = fma2(xx, wA.x, acc[0][dy][dx]);
                        acc[1][dy][dx] = fma2(xx, wA.y, acc[1][dy][dx]);
                        acc[2][dy][dx] = fma2(xx, wB.x, acc[2][dy][dx]);
                        acc[3][dy][dx] = fma2(xx, wB.y, acc[3][dy][dx]);
                        acc[4][dy][dx] = fma2(xx, wC.x, acc[4][dy][dx]);
                        acc[5][dy][dx] = fma2(xx, wC.y, acc[5][dy][dx]);
                        acc[6][dy][dx] = fma2(xx, wD.x, acc[6][dy][dx]);
                        acc[7][dy][dx] = fma2(xx, wD.y, acc[7][dy][dx]);
                    }
                }
            }
        }

        // ---- store prefetched slab s+1
        if (s + 1 < NSLABS) {
            const int q = (s + 1) & 1;
            sx[q][sdst0] = a0;
            sx[q][sdst1] = a1;
            if (has2) sx[q][sdst2] = a2;
            sw2[q][wdst0] = q0;
            if (hw1) sw2[q][wdst1] = q1;
        }
        __syncthreads();
    }

    // ---- ReLU + store: 16 oc x 2x2 px
    const int ocb = ocg * 16;
    const long plane = (long)Z1_ * Z2_ * OH_ * OW_;
    const long ob0 = (((long)b * O_ + ocb) * (Z1_ * Z2_) + (z1 * Z2_ + z2)) * (OH_ * OW_);
#pragma unroll
    for (int o = 0; o < 8; o++) {
        const long obase0 = ob0 + (long)(2 * o)     * plane;
        const long obase1 = ob0 + (long)(2 * o + 1) * plane;
#pragma unroll
        for (int dy = 0; dy < 2; dy++) {
            const int py = h0 + 2 * ph + dy;
            if (py >= OH_) continue;
#pragma unroll
            for (int dx = 0; dx < 2; dx++) {
                const int px = w0 + 2 * pw + dx;
                if (px >= OW_) continue;
                float lo, hi;
                unpack2(lo, hi, acc[o][dy][dx]);
                out[obase0 + py * OW_ + px] = fmaxf(lo, 0.f);
                out[obase1 + py * OW_ + px] = fmaxf(hi, 0.f);
            }
        }
    }
}

extern "C" void kernel_launch(void* const* d_in, const int* in_sizes, int n_in,
                              void* d_out, int out_size)
{
    const float* x   = (const float*)d_in[0];
    const float* wgt = (const float*)d_in[1];
    float* out = (float*)d_out;

    dim3 grid(1, 4, B_ * Z1_ * Z2_);
    // w tiles: 62 -> 2 tiles of 32 (w0 = 0, 32)
    dim3 grid2(2, 4, B_ * Z1_ * Z2_);   // (2,4,72) = 576 blocks
    conv4d_relu_fat_kernel<<<grid2, 256>>>(x, wgt, out);
}

// round 6
// speedup vs baseline: 1.6734x; 1.1346x over previous
#include <cuda_runtime.h>
#include <cuda_bf16.h>
#include <cstdint>

// 4D conv (VALID, stride 1) + ReLU — f32x2 FFMA, cp.async channel-staging.
// in  : [2,16,8,8,64,64] f32
// wgt : [32,16,3,3,3,3]  f32
// out : [2,32,6,6,62,62] f32
//
// Block = (b, z1, z2, 16x32 hw tile), 256 thr = 2 ocg(16 oc) x 128 px-threads
// (1 col x 4 rows each). Stage = one input channel c: 9 (i,j) slabs (18x34,
// padded 36) + 81-tap weights, double-buffered via cp.async; 16 syncs total.
// Weights pre-transposed to [c][tap][oc] by a tiny pre-kernel.

#define SLABW36  36                 // padded slab row stride (16B-aligned)
#define SLAB_F   (18 * SLABW36)     // 648 floats per slab
#define SX_F     (9 * SLAB_F)       // 5832 floats per x buffer
#define SW_F     (81 * 32)          // 2592 floats per weight buffer
#define SMEM_F   (2 * SX_F + 2 * SW_F)   // 16848 floats = 67392 B
#define NXCHUNK  1458               // 9 slabs * 18 rows * 9 chunks
#define NWCHUNK  648                // 2592 / 4

typedef unsigned long long u64;

static __device__ float g_wT[16 * 81 * 32];   // [c][tap81][oc]

__global__ void wtrans_kernel(const float* __restrict__ wgt) {
    const int idx = blockIdx.x * 256 + threadIdx.x;
    if (idx < 16 * 81 * 32) {
        const int oc = idx & 31;
        const int t  = (idx >> 5) % 81;
        const int c  = (idx >> 5) / 81;
        g_wT[idx] = wgt[oc * 1296 + c * 81 + t];
    }
}

__device__ __forceinline__ u64 pack2(float a, float b) {
    u64 r;
    asm("mov.b64 %0, {%1, %2};" : "=l"(r) : "f"(a), "f"(b));
    return r;
}
__device__ __forceinline__ void unpack2(float& lo, float& hi, u64 v) {
    asm("mov.b64 {%0, %1}, %2;" : "=f"(lo), "=f"(hi) : "l"(v));
}
__device__ __forceinline__ u64 fma2(u64 a, u64 b, u64 c) {
    u64 d;
    asm("fma.rn.f32x2 %0, %1, %2, %3;" : "=l"(d) : "l"(a), "l"(b), "l"(c));
    return d;
}
__device__ __forceinline__ void cp_async16(uint32_t dst, const void* src, int n) {
    asm volatile("cp.async.cg.shared.global [%0], [%1], 16, %2;"
                 :: "r"(dst), "l"(src), "r"(n));
}
__device__ __forceinline__ void cp_async8(uint32_t dst, const void* src, int n) {
    asm volatile("cp.async.ca.shared.global [%0], [%1], 8, %2;"
                 :: "r"(dst), "l"(src), "r"(n));
}
#define CP_COMMIT() asm volatile("cp.async.commit_group;")
#define CP_WAIT0()  asm volatile("cp.async.wait_group 0;")

// stage one channel c into the buffers at sx_u32 / sw_u32 (cp.async, zfilled)
__device__ __forceinline__ void stage_channel(
    const float* __restrict__ x, long base0, int c,
    int h0, int w0, int tid, uint32_t sx_u32, uint32_t sw_u32)
{
    const long cbase = base0 + (long)c * 262144;
    const bool w8ok = (w0 + 32) < 64;       // tail cols 32,33 validity
#pragma unroll 1
    for (int k = tid; k < NXCHUNK; k += 256) {
        const int sl  = k / 162;
        const int rem = k - sl * 162;
        const int rr  = rem / 9;
        const int cb  = rem - rr * 9;
        const int i = sl / 3, j = sl - i * 3;
        const float* src = x + cbase + i * 32768 + j * 4096
                             + (h0 + rr) * 64 + w0 + cb * 4;
        const uint32_t dst = sx_u32 + (uint32_t)(sl * SLAB_F + rr * SLABW36 + cb * 4) * 4u;
        const bool rowv = (h0 + rr) < 64;
        if (cb < 8) cp_async16(dst, src, rowv ? 16 : 0);
        else        cp_async8(dst, src, (rowv && w8ok) ? 8 : 0);
    }
#pragma unroll 1
    for (int k = tid; k < NWCHUNK; k += 256)
        cp_async16(sw_u32 + (uint32_t)k * 16u, g_wT + c * 2592 + k * 4, 16);
}

__global__ __launch_bounds__(256, 2)
void conv4d_relu_cp_kernel(const float* __restrict__ x,
                           float* __restrict__ out)
{
    extern __shared__ __align__(16) float smem[];
    float* const sx0 = smem;
    float* const sx1 = smem + SX_F;
    float* const sw0 = smem + 2 * SX_F;
    float* const sw1 = smem + 2 * SX_F + SW_F;
    const uint32_t su = (uint32_t)__cvta_generic_to_shared(smem);
    const uint32_t sxu0 = su;
    const uint32_t sxu1 = su + SX_F * 4;
    const uint32_t swu0 = su + 2 * SX_F * 4;
    const uint32_t swu1 = su + (2 * SX_F + SW_F) * 4;

    const int tid = threadIdx.x;

    // ---- block decode
    const int zb = blockIdx.z;
    const int b  = zb / 36;
    const int zr = zb % 36;
    const int z1 = zr / 6;
    const int z2 = zr % 6;
    const int h0 = blockIdx.y * 16;
    const int w0 = blockIdx.x * 32;

    // ---- thread decode: 2 oc-groups x (4 rows x 1 col) pixel threads
    const int ocg = tid >> 7;            // 0..1 -> oc base = ocg*16
    const int p   = tid & 127;
    const int ph  = p >> 5;              // 0..3 -> rows 4ph..4ph+3
    const int pw  = p & 31;              // 0..31 -> col pw

    const long base0 = (((long)(b * 16) * 8 + z1) * 8 + z2) * 4096;

    // ---- accumulators: 8 oc-pairs x 4 rows (f32x2)
    u64 acc[8][4];
#pragma unroll
    for (int o = 0; o < 8; o++)
#pragma unroll
        for (int dy = 0; dy < 4; dy++)
            acc[o][dy] = 0ull;

    // ---- prologue: stage channel 0
    stage_channel(x, base0, 0, h0, w0, tid, sxu0, swu0);
    CP_COMMIT();
    CP_WAIT0();
    __syncthreads();

#pragma unroll 1
    for (int c = 0; c < 16; c++) {
        const int buf = c & 1;
        // stage next channel into the other buffer (async, fire-and-forget)
        if (c + 1 < 16)
            stage_channel(x, base0, c + 1, h0, w0, tid,
                          buf ? sxu0 : sxu1, buf ? swu0 : swu1);
        CP_COMMIT();

        const float* __restrict__ sxb = buf ? sx1 : sx0;
        const ulonglong2* __restrict__ swq2 =
            (const ulonglong2*)(buf ? sw1 : sw0);

#pragma unroll 1
        for (int sl = 0; sl < 9; sl++) {
            const float* __restrict__ sxp = sxb + sl * SLAB_F + ph * (4 * SLABW36) + pw;
            float xf[6][3];
#pragma unroll
            for (int r = 0; r < 6; r++)
#pragma unroll
                for (int l = 0; l < 3; l++)
                    xf[r][l] = sxp[r * SLABW36 + l];

            const ulonglong2* __restrict__ swt = swq2 + sl * 72 + ocg * 4;
#pragma unroll
            for (int k = 0; k < 3; k++) {
#pragma unroll
                for (int l = 0; l < 3; l++) {
                    const int t = k * 3 + l;
                    const ulonglong2 wA = swt[t * 8 + 0];
                    const ulonglong2 wB = swt[t * 8 + 1];
                    const ulonglong2 wC = swt[t * 8 + 2];
                    const ulonglong2 wD = swt[t * 8 + 3];
#pragma unroll
                    for (int dy = 0; dy < 4; dy++) {
                        const float xv = xf[k + dy][l];
                        const u64 xx = pack2(xv, xv);
                        acc[0][dy] = fma2(xx, wA.x, acc[0][dy]);
                        acc[1][dy] = fma2(xx, wA.y, acc[1][dy]);
                        acc[2][dy] = fma2(xx, wB.x, acc[2][dy]);
                        acc[3][dy] = fma2(xx, wB.y, acc[3][dy]);
                        acc[4][dy] = fma2(xx, wC.x, acc[4][dy]);
                        acc[5][dy] = fma2(xx, wC.y, acc[5][dy]);
                        acc[6][dy] = fma2(xx, wD.x, acc[6][dy]);
                        acc[7][dy] = fma2(xx, wD.y, acc[7][dy]);
                    }
                }
            }
        }

        CP_WAIT0();
        __syncthreads();
    }

    // ---- ReLU + store: 16 oc x 4 rows x 1 col, coalesced in pw
    const int px = w0 + pw;
    if (px < 62) {
        const int ocb = ocg * 16;
        const long ob0 = (((long)b * 32 + ocb) * 36 + (z1 * 6 + z2)) * 3844;
#pragma unroll
        for (int o = 0; o < 8; o++) {
            const long oA = ob0 + (long)(2 * o) * 138384;   // plane = 36*3844
            const long oB = oA + 138384;
#pragma unroll
            for (int dy = 0; dy < 4; dy++) {
                const int py = h0 + 4 * ph + dy;
                if (py < 62) {
                    float lo, hi;
                    unpack2(lo, hi, acc[o][dy]);
                    out[oA + (long)py * 62 + px] = fmaxf(lo, 0.f);
                    out[oB + (long)py * 62 + px] = fmaxf(hi, 0.f);
                }
            }
        }
    }
}

extern "C" void kernel_launch(void* const* d_in, const int* in_sizes, int n_in,
                              void* d_out, int out_size)
{
    const float* x   = (const float*)d_in[0];
    const float* wgt = (const float*)d_in[1];
    float* out = (float*)d_out;

    cudaFuncSetAttribute(conv4d_relu_cp_kernel,
                         cudaFuncAttributeMaxDynamicSharedMemorySize,
                         SMEM_F * 4);

    wtrans_kernel<<<162, 256>>>(wgt);
    conv4d_relu_cp_kernel<<<dim3(2, 4, 72), 256, SMEM_F * 4>>>(x, out);
}

// round 8
// speedup vs baseline: 4.3609x; 2.6060x over previous
#include <cuda_runtime.h>
#include <cstdint>

// 4D conv (VALID, stride 1) + ReLU via mma.sync tf32 implicit GEMM (sm_80+ PTX,
// no arch-'a' features -- tcgen05 unavailable because harness emits compute_103).
// in  : [2,16,8,8,64,64] f32 -> g_xt[b,d1,d2,y,x][c16perm] tf32
// wgt : [32,16,3,3,3,3]  f32 -> g_wT[ij9][kl9][oc32][c16perm] tf32
// out : [2,32,6,6,62,62] f32
//
// CTA = (x-tile{0,32}, y-tile*8, b*z1*z2) of 8 warps; warp = 1 output row x 32px
// (two m16 tiles) x 32 oc (four n8 tiles). K = 81 taps x 16 ch. Channel perm
// (pos 4c+q = ch c+4q) makes every tf32 fragment a single LDS.128.

typedef unsigned int u32;

__device__ float g_xt[2 * 8 * 8 * 64 * 64 * 16];   // 134 MB scratch
__device__ float g_wT[9 * 9 * 32 * 16];

// ---------------- pre-kernels ----------------

__global__ void xt_kernel(const float* __restrict__ x) {
    const int id = blockIdx.x * 256 + threadIdx.x;    // 2,097,152
    const int cq = id & 3;                            // c' = position group
    const int xx = (id >> 2) & 63;
    const int y  = (id >> 8) & 63;
    const int d2 = (id >> 14) & 7;
    const int d1 = (id >> 17) & 7;
    const int b  = id >> 20;
    // positions 4*cq .. 4*cq+3 hold channels cq, cq+4, cq+8, cq+12
    const long sbase = ((((long)(b * 16 + cq) * 8 + d1) * 8 + d2) * 64 + y) * 64 + xx;
    u32 v0, v1, v2, v3;
    asm("cvt.rna.tf32.f32 %0, %1;" : "=r"(v0) : "f"(x[sbase]));
    asm("cvt.rna.tf32.f32 %0, %1;" : "=r"(v1) : "f"(x[sbase + 4 * 262144]));
    asm("cvt.rna.tf32.f32 %0, %1;" : "=r"(v2) : "f"(x[sbase + 8 * 262144]));
    asm("cvt.rna.tf32.f32 %0, %1;" : "=r"(v3) : "f"(x[sbase + 12 * 262144]));
    const long dbase = ((((long)(b * 8 + d1) * 8 + d2) * 64 + y) * 64 + xx) * 16 + cq * 4;
    *reinterpret_cast<uint4*>(&g_xt[dbase]) = make_uint4(v0, v1, v2, v3);
}

__global__ void wt_kernel(const float* __restrict__ wgt) {
    const int id = blockIdx.x * 256 + threadIdx.x;
    if (id >= 9 * 9 * 32 * 16) return;
    const int p  = id & 15;
    const int oc = (id >> 4) & 31;
    const int kl = (id >> 9) % 9;
    const int ij = (id >> 9) / 9;
    const int ch = (p >> 2) + 4 * (p & 3);            // channel permutation
    const float v = wgt[oc * 1296 + ch * 81 + (ij / 3) * 27 + (ij % 3) * 9
                        + (kl / 3) * 3 + (kl % 3)];
    u32 t;
    asm("cvt.rna.tf32.f32 %0, %1;" : "=r"(t) : "f"(v));
    reinterpret_cast<u32*>(g_wT)[id] = t;
}

// ---------------- helpers ----------------

__device__ __forceinline__ void cp_async16(u32 dst, const void* src, int n) {
    asm volatile("cp.async.cg.shared.global [%0], [%1], 16, %2;"
                 :: "r"(dst), "l"(src), "r"(n));
}

#define MMA_TF32(d, a0, a1, a2, a3, b0, b1)                                   \
    asm volatile(                                                             \
        "mma.sync.aligned.m16n8k8.row.col.f32.tf32.tf32.f32 "                 \
        "{%0,%1,%2,%3}, {%4,%5,%6,%7}, {%8,%9}, {%0,%1,%2,%3};"               \
        : "+f"((d)[0]), "+f"((d)[1]), "+f"((d)[2]), "+f"((d)[3])              \
        : "r"(a0), "r"(a1), "r"(a2), "r"(a3), "r"(b0), "r"(b1))

#define SXF 5440     // 10 rows * 34 px * 16 floats
#define SWF 4608     // 9 taps * 32 oc * 16 floats
#define NXC 1360     // 10*34*4 16B chunks
#define NWC 1152     // 4608/4
#define SMEM_BYTES ((2 * SXF + 2 * SWF) * 4)   // 80384

// ---------------- main kernel ----------------

__global__ __launch_bounds__(256, 2)
void conv4d_tf32_wmma_kernel(float* __restrict__ out)
{
    extern __shared__ __align__(16) float smem[];
    float* const sxb[2] = { smem, smem + SXF };
    float* const swb[2] = { smem + 2 * SXF, smem + 2 * SXF + SWF };
    const u32 su = (u32)__cvta_generic_to_shared(smem);

    const int tid  = threadIdx.x;
    const int w    = tid >> 5;          // warp -> output row offset
    const int lane = tid & 31;
    const int lg   = lane >> 2;         // groupID
    const int tg   = lane & 3;          // threadID-in-group

    const int x0 = 32 * blockIdx.x;     // 0, 32
    const int y0 = 8 * blockIdx.y;      // 0..56
    const int zb = blockIdx.z;
    const int b  = zb / 36;
    const int zr = zb % 36;
    const int z1 = zr / 6, z2 = zr % 6;

    float acc[2][4][4];
#pragma unroll
    for (int mt = 0; mt < 2; mt++)
#pragma unroll
        for (int n = 0; n < 4; n++)
#pragma unroll
            for (int r = 0; r < 4; r++)
                acc[mt][n][r] = 0.f;

    // ---- staging lambda-ish macro (ij -> buffer buf)
#define STAGE(IJ, BUF) do {                                                   \
    const int i_ = (IJ) / 3, j_ = (IJ) % 3;                                   \
    const long xgb = (((long)(b * 8 + z1 + i_) * 8 + (z2 + j_)) * 4096) * 16; \
    const u32 sxu = su + (BUF) * (SXF * 4);                                   \
    const u32 swu = su + (2 * SXF + (BUF) * SWF) * 4;                         \
    for (int k = tid; k < NXC + NWC; k += 256) {                              \
        if (k < NXC) {                                                        \
            const int ry = k / 136;                                           \
            const int rem = k - ry * 136;                                     \
            const int px = rem >> 2;                                          \
            const int pg = rem & 3;                                           \
            const int gy = y0 + ry, gx = x0 + px;                             \
            const float* src = g_xt + xgb + ((long)gy * 64 + gx) * 16 + pg * 4;\
            cp_async16(sxu + (u32)((ry * 34 + px) * 64 + pg * 16), src,       \
                       (gy < 64 && gx < 64) ? 16 : 0);                        \
        } else {                                                              \
            const int kw = k - NXC;                                           \
            cp_async16(swu + (u32)(kw * 16), g_wT + (IJ) * 4608 + kw * 4, 16);\
        }                                                                     \
    }                                                                         \
} while (0)

    STAGE(0, 0);
    asm volatile("cp.async.commit_group;");

#pragma unroll 1
    for (int ij = 0; ij < 9; ij++) {
        const int buf = ij & 1;
        if (ij + 1 < 9) STAGE(ij + 1, buf ^ 1);
        asm volatile("cp.async.commit_group;");
        asm volatile("cp.async.wait_group 1;");
        __syncthreads();

        const float* __restrict__ sx = sxb[buf];
        const float* __restrict__ sw = swb[buf];
        const int aoff = lg * 16 + tg * 4;   // float offset within a position row

#pragma unroll
        for (int kl = 0; kl < 9; kl++) {
            const int kk = kl / 3, ll = kl % 3;
            const int arow = ((w + kk) * 34 + ll) * 16;

            // A fragments: [mt][half], 4 x LDS.128 (conflict-free)
            const float4 a00 = *(const float4*)(sx + arow + aoff);
            const float4 a01 = *(const float4*)(sx + arow + aoff + 8 * 16);
            const float4 a10 = *(const float4*)(sx + arow + aoff + 16 * 16);
            const float4 a11 = *(const float4*)(sx + arow + aoff + 24 * 16);

            // B fragments: 4 n-tiles, 4 x LDS.128
            const float* wt = sw + kl * 512 + aoff;
            const float4 b0 = *(const float4*)(wt);
            const float4 b1 = *(const float4*)(wt + 128);
            const float4 b2 = *(const float4*)(wt + 256);
            const float4 b3 = *(const float4*)(wt + 384);

#pragma unroll
            for (int mt = 0; mt < 2; mt++) {
                const float4 ah0 = mt ? a10 : a00;
                const float4 ah1 = mt ? a11 : a01;
                const u32 p00 = __float_as_uint(ah0.x), p02 = __float_as_uint(ah0.y);
                const u32 p01 = __float_as_uint(ah1.x), p03 = __float_as_uint(ah1.y);
                const u32 q00 = __float_as_uint(ah0.z), q02 = __float_as_uint(ah0.w);
                const u32 q01 = __float_as_uint(ah1.z), q03 = __float_as_uint(ah1.w);
                // kstep0 (channels c', c'+4)
                MMA_TF32(acc[mt][0], p00, p01, p02, p03,
                         __float_as_uint(b0.x), __float_as_uint(b0.y));
                MMA_TF32(acc[mt][1], p00, p01, p02, p03,
                         __float_as_uint(b1.x), __float_as_uint(b1.y));
                MMA_TF32(acc[mt][2], p00, p01, p02, p03,
                         __float_as_uint(b2.x), __float_as_uint(b2.y));
                MMA_TF32(acc[mt][3], p00, p01, p02, p03,
                         __float_as_uint(b3.x), __float_as_uint(b3.y));
                // kstep1 (channels c'+8, c'+12)
                MMA_TF32(acc[mt][0], q00, q01, q02, q03,
                         __float_as_uint(b0.z), __float_as_uint(b0.w));
                MMA_TF32(acc[mt][1], q00, q01, q02, q03,
                         __float_as_uint(b1.z), __float_as_uint(b1.w));
                MMA_TF32(acc[mt][2], q00, q01, q02, q03,
                         __float_as_uint(b2.z), __float_as_uint(b2.w));
                MMA_TF32(acc[mt][3], q00, q01, q02, q03,
                         __float_as_uint(b3.z), __float_as_uint(b3.w));
            }
        }
        __syncthreads();
    }

    // ---- epilogue: ReLU + store (D frag: row=lg(+8), col=2*tg(+1))
    const int y = y0 + w;
    if (y < 62) {
        const long ob = (long)b * 4428288 + (z1 * 6 + z2) * 3844 + (long)y * 62;
#pragma unroll
        for (int mt = 0; mt < 2; mt++) {
            const int px0 = x0 + mt * 16 + lg;
            const int px8 = px0 + 8;
#pragma unroll
            for (int n = 0; n < 4; n++) {
                const int oc = n * 8 + 2 * tg;
                const long o0 = ob + (long)oc * 138384;
                if (px0 < 62) {
                    out[o0 + px0]          = fmaxf(acc[mt][n][0], 0.f);
                    out[o0 + 138384 + px0] = fmaxf(acc[mt][n][1], 0.f);
                }
                if (px8 < 62) {
                    out[o0 + px8]          = fmaxf(acc[mt][n][2], 0.f);
                    out[o0 + 138384 + px8] = fmaxf(acc[mt][n][3], 0.f);
                }
            }
        }
    }
}

extern "C" void kernel_launch(void* const* d_in, const int* in_sizes, int n_in,
                              void* d_out, int out_size)
{
    const float* x   = (const float*)d_in[0];
    const float* wgt = (const float*)d_in[1];
    float* out = (float*)d_out;

    cudaFuncSetAttribute(conv4d_tf32_wmma_kernel,
                         cudaFuncAttributeMaxDynamicSharedMemorySize, SMEM_BYTES);

    xt_kernel<<<8192, 256>>>(x);
    wt_kernel<<<162, 256>>>(wgt);
    conv4d_tf32_wmma_kernel<<<dim3(2, 8, 72), 256, SMEM_BYTES>>>(out);
}

// round 9
// speedup vs baseline: 9.1019x; 2.0872x over previous
#include <cuda_runtime.h>
#include <cuda_fp16.h>
#include <cstdint>

// 4D conv (VALID, stride 1) + ReLU via mma.sync m16n8k16 fp16 (fp32 accum).
// in  : [2,16,8,8,64,64] f32 -> g_xh[b,d1,d2,y,x][c16perm] fp16
// wgt : [32,16,3,3,3,3]  f32 -> g_wh[ij9][kl9][oc32][c16perm] fp16
// out : [2,32,6,6,62,62] f32
//
// Channel perm: stored quad 4t..4t+3 = channels {2t,2t+1,2t+8,2t+9} so every
// A/B fragment is one 8B (uint2) conflict-free LDS.64 per thread.
// CTA = (x-tile{0,32}, 16-row y-tile, b*z1*z2); warp = 2 rows x 32 px (4 m16
// tiles) x 32 oc (4 n8 tiles); K = 81 taps x 16 ch, 9 ij cp.async stages.

typedef unsigned int u32;

__device__ __half g_xh[2 * 8 * 8 * 64 * 64 * 16];   // 67 MB scratch
__device__ __half g_wh[9 * 9 * 32 * 16];

// ---------------- pre-kernels ----------------

__global__ void xh_kernel(const float* __restrict__ x) {
    const int id = blockIdx.x * 256 + threadIdx.x;    // 524288 positions
    const int xx = id & 63;
    const int y  = (id >> 6) & 63;
    const int d2 = (id >> 12) & 7;
    const int d1 = (id >> 15) & 7;
    const int b  = id >> 18;
    const long sp = ((((long)b * 16) * 8 + d1) * 8 + d2) * 4096 + y * 64 + xx;
    float v[16];
#pragma unroll
    for (int c = 0; c < 16; c++)
        v[c] = x[sp + (long)c * 262144];
    __half2 h[8];
#pragma unroll
    for (int t = 0; t < 4; t++) {
        h[2 * t]     = __floats2half2_rn(v[2 * t],     v[2 * t + 1]);
        h[2 * t + 1] = __floats2half2_rn(v[2 * t + 8], v[2 * t + 9]);
    }
    const long dbase = ((((long)(b * 8 + d1) * 8 + d2) * 64 + y) * 64 + xx) * 16;
    uint4* dst = reinterpret_cast<uint4*>(g_xh + dbase);
    const u32* hu = reinterpret_cast<const u32*>(h);
    dst[0] = make_uint4(hu[0], hu[1], hu[2], hu[3]);
    dst[1] = make_uint4(hu[4], hu[5], hu[6], hu[7]);
}

__global__ void wh_kernel(const float* __restrict__ wgt) {
    const int id = blockIdx.x * 256 + threadIdx.x;
    if (id >= 9 * 9 * 32 * 16) return;
    const int p  = id & 15;
    const int oc = (id >> 4) & 31;
    const int kl = (id >> 9) % 9;
    const int ij = (id >> 9) / 9;
    const int t  = p >> 2, u = p & 3;
    const int ch = (u < 2) ? (2 * t + u) : (2 * t + 6 + u);   // perm
    const float v = wgt[oc * 1296 + ch * 81 + (ij / 3) * 27 + (ij % 3) * 9
                        + (kl / 3) * 3 + (kl % 3)];
    g_wh[id] = __float2half_rn(v);
}

// ---------------- helpers ----------------

__device__ __forceinline__ void cp_async16(u32 dst, const void* src, int n) {
    asm volatile("cp.async.cg.shared.global [%0], [%1], 16, %2;"
                 :: "r"(dst), "l"(src), "r"(n));
}

#define MMA_F16(d, a0, a1, a2, a3, b0, b1)                                    \
    asm volatile(                                                             \
        "mma.sync.aligned.m16n8k16.row.col.f32.f16.f16.f32 "                  \
        "{%0,%1,%2,%3}, {%4,%5,%6,%7}, {%8,%9}, {%0,%1,%2,%3};"               \
        : "+f"((d)[0]), "+f"((d)[1]), "+f"((d)[2]), "+f"((d)[3])              \
        : "r"(a0), "r"(a1), "r"(a2), "r"(a3), "r"(b0), "r"(b1))

#define SXH 9792     // 18 rows * 34 pos * 16 halves
#define SWH 4608     // 9 taps * 32 oc * 16 halves
#define SMEM_BYTES (2 * (SXH + SWH) * 2)   // 57600

// ---------------- main kernel ----------------

__global__ __launch_bounds__(256, 2)
void conv4d_f16_mma_kernel(float* __restrict__ out)
{
    extern __shared__ __align__(16) __half smh[];
    const u32 su = (u32)__cvta_generic_to_shared(smh);

    const int tid  = threadIdx.x;
    const int w    = tid >> 5;          // warp 0..7 -> rows 2w, 2w+1
    const int lane = tid & 31;
    const int lg   = lane >> 2;
    const int tg   = lane & 3;
    const int w2   = 2 * w;

    const int x0 = 32 * blockIdx.x;     // 0, 32
    const int y0 = 16 * blockIdx.y;     // 0, 16, 32, 48
    const int zb = blockIdx.z;
    const int b  = zb / 36;
    const int zr = zb % 36;
    const int z1 = zr / 6, z2 = zr % 6;

    float acc[4][4][4];
#pragma unroll
    for (int mt = 0; mt < 4; mt++)
#pragma unroll
        for (int n = 0; n < 4; n++)
#pragma unroll
            for (int r = 0; r < 4; r++)
                acc[mt][n][r] = 0.f;

#define STAGE(IJ, BUF) do {                                                   \
    const int i_ = (IJ) / 3, j_ = (IJ) % 3;                                   \
    const long xgb = (((long)(b * 8 + z1 + i_) * 8 + (z2 + j_)) * 4096) * 16; \
    const u32 sxu = su + (BUF) * (SXH * 2);                                   \
    const u32 swu = su + 2 * SXH * 2 + (BUF) * (SWH * 2);                     \
    for (int k = tid; k < 1800; k += 256) {                                   \
        if (k < 1224) {                                                       \
            const int ry = k / 68;                                            \
            const int rem = k - ry * 68;                                      \
            const int pos = rem >> 1;                                         \
            const int hf = rem & 1;                                           \
            const int gy = y0 + ry, gx = x0 + pos;                            \
            const __half* src = g_xh + xgb + ((long)gy * 64 + gx) * 16 + hf * 8;\
            cp_async16(sxu + (u32)((ry * 34 + pos) * 32 + hf * 16), src,      \
                       (gy < 64 && gx < 64) ? 16 : 0);                        \
        } else {                                                              \
            const int kw = k - 1224;                                          \
            cp_async16(swu + (u32)(kw * 16), g_wh + (IJ) * 4608 + kw * 8, 16);\
        }                                                                     \
    }                                                                         \
} while (0)

    STAGE(0, 0);
    asm volatile("cp.async.commit_group;");

    const int poff = lg * 16 + tg * 4;   // half offset within an A row segment
    const int qoff = lg * 16 + tg * 4;   // half offset within a B n-tile

#pragma unroll 1
    for (int ij = 0; ij < 9; ij++) {
        const int buf = ij & 1;
        if (ij + 1 < 9) STAGE(ij + 1, buf ^ 1);
        asm volatile("cp.async.commit_group;");
        asm volatile("cp.async.wait_group 1;");
        __syncthreads();

        const __half* __restrict__ sx = smh + buf * SXH;
        const __half* __restrict__ sw = smh + 2 * SXH + buf * SWH;

#pragma unroll
        for (int kl = 0; kl < 9; kl++) {
            const int kk = kl / 3, ll = kl % 3;
            const __half* axp = sx + ((w2 + kk) * 34 + ll) * 16 + poff;

            uint2 A[4][2];
            A[0][0] = *(const uint2*)(axp);
            A[0][1] = *(const uint2*)(axp + 128);
            A[1][0] = *(const uint2*)(axp + 256);
            A[1][1] = *(const uint2*)(axp + 384);
            A[2][0] = *(const uint2*)(axp + 544);
            A[2][1] = *(const uint2*)(axp + 672);
            A[3][0] = *(const uint2*)(axp + 800);
            A[3][1] = *(const uint2*)(axp + 928);

            const __half* swp = sw + kl * 512 + qoff;
            const uint2 B0 = *(const uint2*)(swp);
            const uint2 B1 = *(const uint2*)(swp + 128);
            const uint2 B2 = *(const uint2*)(swp + 256);
            const uint2 B3 = *(const uint2*)(swp + 384);

#pragma unroll
            for (int mt = 0; mt < 4; mt++) {
                const u32 a0 = A[mt][0].x, a1 = A[mt][1].x;
                const u32 a2 = A[mt][0].y, a3 = A[mt][1].y;
                MMA_F16(acc[mt][0], a0, a1, a2, a3, B0.x, B0.y);
                MMA_F16(acc[mt][1], a0, a1, a2, a3, B1.x, B1.y);
                MMA_F16(acc[mt][2], a0, a1, a2, a3, B2.x, B2.y);
                MMA_F16(acc[mt][3], a0, a1, a2, a3, B3.x, B3.y);
            }
        }
        __syncthreads();
    }

    // ---- epilogue: ReLU + store
    const long ob = (long)b * 4428288 + (z1 * 6 + z2) * 3844;
#pragma unroll
    for (int mt = 0; mt < 4; mt++) {
        const int y = y0 + w2 + (mt >> 1);
        if (y >= 62) continue;
        const int px0 = x0 + (mt & 1) * 16 + lg;
        const int px8 = px0 + 8;
#pragma unroll
        for (int n = 0; n < 4; n++) {
            const int oc = n * 8 + 2 * tg;
            const long o0 = ob + (long)oc * 138384 + (long)y * 62;
            if (px0 < 62) {
                out[o0 + px0]          = fmaxf(acc[mt][n][0], 0.f);
                out[o0 + 138384 + px0] = fmaxf(acc[mt][n][1], 0.f);
            }
            if (px8 < 62) {
                out[o0 + px8]          = fmaxf(acc[mt][n][2], 0.f);
                out[o0 + 138384 + px8] = fmaxf(acc[mt][n][3], 0.f);
            }
        }
    }
}

extern "C" void kernel_launch(void* const* d_in, const int* in_sizes, int n_in,
                              void* d_out, int out_size)
{
    const float* x   = (const float*)d_in[0];
    const float* wgt = (const float*)d_in[1];
    float* out = (float*)d_out;

    cudaFuncSetAttribute(conv4d_f16_mma_kernel,
                         cudaFuncAttributeMaxDynamicSharedMemorySize, SMEM_BYTES);

    xh_kernel<<<2048, 256>>>(x);
    wh_kernel<<<162, 256>>>(wgt);
    conv4d_f16_mma_kernel<<<dim3(2, 4, 72), 256, SMEM_BYTES>>>(out);
}

// round 10
// speedup vs baseline: 9.6840x; 1.0640x over previous
#include <cuda_runtime.h>
#include <cuda_fp16.h>
#include <cstdint>

// 4D conv (VALID, stride 1) + ReLU via mma.sync m16n8k16 fp16 (fp32 accum),
// staging via cp.async.bulk (TMA) + mbarrier, triple-buffered.
// in  : [2,16,8,8,64,64] f32 -> g_xh[b,d1,d2,y,x][c16perm] fp16 (padded tail)
// wgt : [32,16,3,3,3,3]  f32 -> g_wh[ij9][kl9][oc32][c16perm] fp16
// out : [2,32,6,6,62,62] f32
//
// CTA = (x-tile{0,32}, 16-row y-tile, b*z1*z2); warp = 2 rows x 32 px (4 m16
// tiles) x 32 oc (4 n8 tiles); K = 81 taps x 16 ch. Stage = one (i,j) window:
// 18 x 1088B x-rows + 9216B weights = 19 bulk copies, 28800 B. Edge tiles
// over-read finite neighbor/pad data that only feeds discarded outputs.

typedef unsigned int u32;

__device__ __half g_xh[2 * 8 * 8 * 64 * 64 * 16 + 4096];   // +8KB pad
__device__ __half g_wh[9 * 9 * 32 * 16];

// ---------------- pre-kernels ----------------

__global__ void xh_kernel(const float* __restrict__ x) {
    const int id = blockIdx.x * 256 + threadIdx.x;    // 524288 positions
    const int xx = id & 63;
    const int y  = (id >> 6) & 63;
    const int d2 = (id >> 12) & 7;
    const int d1 = (id >> 15) & 7;
    const int b  = id >> 18;
    const long sp = ((((long)b * 16) * 8 + d1) * 8 + d2) * 4096 + y * 64 + xx;
    float v[16];
#pragma unroll
    for (int c = 0; c < 16; c++)
        v[c] = x[sp + (long)c * 262144];
    __half2 h[8];
#pragma unroll
    for (int t = 0; t < 4; t++) {
        h[2 * t]     = __floats2half2_rn(v[2 * t],     v[2 * t + 1]);
        h[2 * t + 1] = __floats2half2_rn(v[2 * t + 8], v[2 * t + 9]);
    }
    const long dbase = ((((long)(b * 8 + d1) * 8 + d2) * 64 + y) * 64 + xx) * 16;
    uint4* dst = reinterpret_cast<uint4*>(g_xh + dbase);
    const u32* hu = reinterpret_cast<const u32*>(h);
    dst[0] = make_uint4(hu[0], hu[1], hu[2], hu[3]);
    dst[1] = make_uint4(hu[4], hu[5], hu[6], hu[7]);
}

__global__ void wh_kernel(const float* __restrict__ wgt) {
    const int id = blockIdx.x * 256 + threadIdx.x;
    if (id >= 9 * 9 * 32 * 16) return;
    const int p  = id & 15;
    const int oc = (id >> 4) & 31;
    const int kl = (id >> 9) % 9;
    const int ij = (id >> 9) / 9;
    const int t  = p >> 2, u = p & 3;
    const int ch = (u < 2) ? (2 * t + u) : (2 * t + 6 + u);   // perm
    const float v = wgt[oc * 1296 + ch * 81 + (ij / 3) * 27 + (ij % 3) * 9
                        + (kl / 3) * 3 + (kl % 3)];
    g_wh[id] = __float2half_rn(v);
}

// ---------------- helpers ----------------

__device__ __forceinline__ void bulk_g2s(u32 dst, const void* src, u32 bytes, u32 mbar) {
    asm volatile(
        "cp.async.bulk.shared::cluster.global.mbarrier::complete_tx::bytes "
        "[%0], [%1], %2, [%3];"
        :: "r"(dst), "l"(src), "r"(bytes), "r"(mbar) : "memory");
}
__device__ __forceinline__ void mbar_init(u32 mbar, u32 cnt) {
    asm volatile("mbarrier.init.shared.b64 [%0], %1;" :: "r"(mbar), "r"(cnt) : "memory");
}
__device__ __forceinline__ void mbar_expect(u32 mbar, u32 bytes) {
    asm volatile("mbarrier.arrive.expect_tx.shared.b64 _, [%0], %1;"
                 :: "r"(mbar), "r"(bytes) : "memory");
}
__device__ __forceinline__ void mbar_wait(u32 mbar, u32 parity) {
    u32 done;
    asm volatile(
        "{\n\t.reg .pred p;\n\t"
        "mbarrier.try_wait.parity.acquire.cta.shared::cta.b64 p, [%1], %2;\n\t"
        "selp.b32 %0, 1, 0, p;\n\t}"
        : "=r"(done) : "r"(mbar), "r"(parity) : "memory");
    if (!done) {
        asm volatile(
            "{\n\t.reg .pred P1;\n\t"
            "WL_%=:\n\t"
            "mbarrier.try_wait.parity.acquire.cta.shared::cta.b64 P1, [%0], %1, 0x989680;\n\t"
            "@P1 bra.uni WD_%=;\n\t"
            "bra.uni WL_%=;\n\t"
            "WD_%=:\n\t}"
            :: "r"(mbar), "r"(parity) : "memory");
    }
}

#define MMA_F16(d, a0, a1, a2, a3, b0, b1)                                    \
    asm volatile(                                                             \
        "mma.sync.aligned.m16n8k16.row.col.f32.f16.f16.f32 "                  \
        "{%0,%1,%2,%3}, {%4,%5,%6,%7}, {%8,%9}, {%0,%1,%2,%3};"               \
        : "+f"((d)[0]), "+f"((d)[1]), "+f"((d)[2]), "+f"((d)[3])              \
        : "r"(a0), "r"(a1), "r"(a2), "r"(a3), "r"(b0), "r"(b1))

#define SXH 9792          // 18 rows * 34 pos * 16 halves
#define SWH 4608          // 9 taps * 32 oc * 16 halves
#define BUFH (SXH + SWH)  // 14400 halves = 28800 B
#define STAGE_BYTES 28800u
#define SMEM_BYTES (3 * BUFH * 2)   // 86400

// ---------------- main kernel ----------------

__global__ __launch_bounds__(256, 2)
void conv4d_f16_tma_kernel(float* __restrict__ out)
{
    extern __shared__ __align__(128) __half smh[];
    __shared__ __align__(8) unsigned long long s_mbar[3];

    const u32 su = (u32)__cvta_generic_to_shared(smh);
    const u32 mb = (u32)__cvta_generic_to_shared(s_mbar);

    const int tid  = threadIdx.x;
    const int w    = tid >> 5;          // warp 0..7 -> rows 2w, 2w+1
    const int lane = tid & 31;
    const int lg   = lane >> 2;
    const int tg   = lane & 3;
    const int w2   = 2 * w;

    const int x0 = 32 * blockIdx.x;     // 0, 32
    const int y0 = 16 * blockIdx.y;     // 0, 16, 32, 48
    const int zb = blockIdx.z;
    const int b  = zb / 36;
    const int zr = zb % 36;
    const int z1 = zr / 6, z2 = zr % 6;

    if (tid == 0) {
        mbar_init(mb,      1u);
        mbar_init(mb + 8,  1u);
        mbar_init(mb + 16, 1u);
    }
    __syncthreads();

    // issue stage k (thread 0 only): 18 x-rows + 1 weight block
#define ISSUE(K) do {                                                         \
    const int i_ = (K) / 3, j_ = (K) % 3;                                     \
    const long xgb = (((long)(b * 8 + z1 + i_) * 8 + (z2 + j_)) * 4096) * 16; \
    const u32 bufu = su + (u32)((K) % 3) * (BUFH * 2);                        \
    const u32 m = mb + (u32)((K) % 3) * 8;                                    \
    mbar_expect(m, STAGE_BYTES);                                              \
    const __half* xsrc = g_xh + xgb + ((long)y0 * 64 + x0) * 16;              \
    for (int ry = 0; ry < 18; ry++)                                           \
        bulk_g2s(bufu + ry * 1088, xsrc + (long)ry * 1024, 1088, m);          \
    bulk_g2s(bufu + SXH * 2, g_wh + (K) * 4608, 9216, m);                     \
} while (0)

    if (tid == 0) { ISSUE(0); ISSUE(1); }

    float acc[4][4][4];
#pragma unroll
    for (int mt = 0; mt < 4; mt++)
#pragma unroll
        for (int n = 0; n < 4; n++)
#pragma unroll
            for (int r = 0; r < 4; r++)
                acc[mt][n][r] = 0.f;

    const int poff = lg * 16 + tg * 4;

#pragma unroll 1
    for (int ij = 0; ij < 9; ij++) {
        mbar_wait(mb + (u32)(ij % 3) * 8, (u32)((ij / 3) & 1));

        const __half* __restrict__ sx = smh + (ij % 3) * BUFH;
        const __half* __restrict__ sw = sx + SXH;

#pragma unroll
        for (int kl = 0; kl < 9; kl++) {
            const int kk = kl / 3, ll = kl % 3;
            const __half* axp = sx + ((w2 + kk) * 34 + ll) * 16 + poff;

            uint2 A[4][2];
            A[0][0] = *(const uint2*)(axp);
            A[0][1] = *(const uint2*)(axp + 128);
            A[1][0] = *(const uint2*)(axp + 256);
            A[1][1] = *(const uint2*)(axp + 384);
            A[2][0] = *(const uint2*)(axp + 544);
            A[2][1] = *(const uint2*)(axp + 672);
            A[3][0] = *(const uint2*)(axp + 800);
            A[3][1] = *(const uint2*)(axp + 928);

            const __half* swp = sw + kl * 512 + poff;
            const uint2 B0 = *(const uint2*)(swp);
            const uint2 B1 = *(const uint2*)(swp + 128);
            const uint2 B2 = *(const uint2*)(swp + 256);
            const uint2 B3 = *(const uint2*)(swp + 384);

#pragma unroll
            for (int mt = 0; mt < 4; mt++) {
                const u32 a0 = A[mt][0].x, a1 = A[mt][1].x;
                const u32 a2 = A[mt][0].y, a3 = A[mt][1].y;
                MMA_F16(acc[mt][0], a0, a1, a2, a3, B0.x, B0.y);
                MMA_F16(acc[mt][1], a0, a1, a2, a3, B1.x, B1.y);
                MMA_F16(acc[mt][2], a0, a1, a2, a3, B2.x, B2.y);
                MMA_F16(acc[mt][3], a0, a1, a2, a3, B3.x, B3.y);
            }
        }

        __syncthreads();                 // all warps done reading buf ij%3
        if (ij + 2 < 9 && tid == 0) ISSUE(ij + 2);
    }

    // ---- epilogue: ReLU + store
    const long ob = (long)b * 4428288 + (z1 * 6 + z2) * 3844;
#pragma unroll
    for (int mt = 0; mt < 4; mt++) {
        const int y = y0 + w2 + (mt >> 1);
        if (y >= 62) continue;
        const int px0 = x0 + (mt & 1) * 16 + lg;
        const int px8 = px0 + 8;
#pragma unroll
        for (int n = 0; n < 4; n++) {
            const int oc = n * 8 + 2 * tg;
            const long o0 = ob + (long)oc * 138384 + (long)y * 62;
            if (px0 < 62) {
                out[o0 + px0]          = fmaxf(acc[mt][n][0], 0.f);
                out[o0 + 138384 + px0] = fmaxf(acc[mt][n][1], 0.f);
            }
            if (px8 < 62) {
                out[o0 + px8]          = fmaxf(acc[mt][n][2], 0.f);
                out[o0 + 138384 + px8] = fmaxf(acc[mt][n][3], 0.f);
            }
        }
    }
}

extern "C" void kernel_launch(void* const* d_in, const int* in_sizes, int n_in,
                              void* d_out, int out_size)
{
    const float* x   = (const float*)d_in[0];
    const float* wgt = (const float*)d_in[1];
    float* out = (float*)d_out;

    cudaFuncSetAttribute(conv4d_f16_tma_kernel,
                         cudaFuncAttributeMaxDynamicSharedMemorySize, SMEM_BYTES);

    xh_kernel<<<2048, 256>>>(x);
    wh_kernel<<<162, 256>>>(wgt);
    conv4d_f16_tma_kernel<<<dim3(2, 4, 72), 256, SMEM_BYTES>>>(out);
}